// round 1
// baseline (speedup 1.0000x reference)
#include <cuda_runtime.h>
#include <math.h>

#define NN 50000
#define NE 600000
#define NC 500
#define CE 8000
#define EPSV 1e-5f

// ---------------- scratch (static device globals; no runtime alloc) ----------------
__device__ float g_bufA[NN*128];
__device__ float g_bufB[NN*128];
__device__ float g_agg [NN*128];
__device__ float g_tmp [NN*128];
__device__ float g_cA  [NC*128];
__device__ float g_cB  [NC*128];
__device__ float g_cagg[NC*128];
__device__ float g_ctmp[NC*128];
__device__ float g_qkv [(size_t)2*NN*384];
__device__ float g_hfinal[NN*128];
__device__ float g_z1  [NN*64];
__device__ int   g_degN [NN];
__device__ int   g_offN [NN+1];
__device__ int   g_fillN[NN];
__device__ int   g_colN [NE];
__device__ float g_wN   [NE];
__device__ float g_dinvN[NN];
__device__ int   g_degC [NC];
__device__ int   g_offC [NC+1];
__device__ int   g_fillC[NC];
__device__ int   g_colC [CE];
__device__ float g_wC   [CE];
__device__ float g_dinvC[NC];
__device__ float g_stats[7*256];
__device__ float g_WiT[128*384];
__device__ float g_WoT[128*128];

// ---------------- graph prep ----------------
__global__ void zero_kernel() {
    int i = blockIdx.x*blockDim.x + threadIdx.x;
    if (i < NN) { g_degN[i] = 0; g_fillN[i] = 0; }
    if (i < NC) { g_degC[i] = 0; g_fillC[i] = 0; }
    if (i < 7*256) g_stats[i] = 0.f;
}

__global__ void count_deg_kernel(const int* __restrict__ dst, int* __restrict__ deg, int ne) {
    int e = blockIdx.x*blockDim.x + threadIdx.x;
    if (e < ne) atomicAdd(&deg[dst[e]], 1);
}

// single-block exclusive scan, writes off[0..n] (off[n] = total)
__global__ void scan_kernel(const int* __restrict__ cnt, int* __restrict__ off, int n) {
    __shared__ int s[1024];
    __shared__ int carry;
    int tid = threadIdx.x;
    if (tid == 0) carry = 0;
    __syncthreads();
    for (int base = 0; base < n; base += 1024) {
        int cbase = carry;
        int i = base + tid;
        int v = (i < n) ? cnt[i] : 0;
        s[tid] = v; __syncthreads();
        #pragma unroll
        for (int d = 1; d < 1024; d <<= 1) {
            int add = (tid >= d) ? s[tid - d] : 0;
            __syncthreads();
            s[tid] += add;
            __syncthreads();
        }
        if (i < n) off[i] = cbase + s[tid] - v;
        if (tid == 0) carry = cbase + s[1023];
        __syncthreads();
    }
    if (threadIdx.x == 0) off[n] = carry;
}

__global__ void dinv_kernel(const int* __restrict__ deg, float* __restrict__ dinv, int n) {
    int i = blockIdx.x*blockDim.x + threadIdx.x;
    if (i < n) dinv[i] = 1.0f / sqrtf((float)(deg[i] + 1));  // +1 self loop
}

__global__ void fill_csr_kernel(const int* __restrict__ src, const int* __restrict__ dst,
                                const int* __restrict__ off, int* __restrict__ fill,
                                int* __restrict__ col, float* __restrict__ w,
                                const float* __restrict__ dinv, int ne) {
    int e = blockIdx.x*blockDim.x + threadIdx.x;
    if (e >= ne) return;
    int s = src[e], d = dst[e];
    int pos = off[d] + atomicAdd(&fill[d], 1);
    col[pos] = s;
    w[pos] = dinv[s] * dinv[d];
}

__global__ void transpose_w_kernel(const float* __restrict__ wi, const float* __restrict__ wo) {
    int idx = blockIdx.x*blockDim.x + threadIdx.x;
    if (idx < 384*128) { int j = idx / 128, k = idx % 128; g_WiT[k*384 + j] = wi[idx]; }
    if (idx < 128*128) { int j = idx / 128, k = idx % 128; g_WoT[k*128 + j] = wo[idx]; }
}

// ---------------- GCN aggregation: agg[i] = dinv_i^2 h[i] + sum_e w_e h[src_e] ----------------
__global__ void gcn_agg_kernel(const float* __restrict__ h, float* __restrict__ agg,
                               const int* __restrict__ off, const int* __restrict__ col,
                               const float* __restrict__ w, const float* __restrict__ dinv, int n) {
    int wid = (blockIdx.x*blockDim.x + threadIdx.x) >> 5;
    int lane = threadIdx.x & 31;
    if (wid >= n) return;
    float dv = dinv[wid];
    float sw = dv * dv;
    float4 hv = *(const float4*)(h + (size_t)wid*128 + lane*4);
    float4 acc = make_float4(sw*hv.x, sw*hv.y, sw*hv.z, sw*hv.w);
    int s = off[wid], e = off[wid+1];
    for (int j = s; j < e; j++) {
        int src = col[j];
        float ww = w[j];
        float4 xv = *(const float4*)(h + (size_t)src*128 + lane*4);
        acc.x += ww*xv.x; acc.y += ww*xv.y; acc.z += ww*xv.z; acc.w += ww*xv.w;
    }
    *(float4*)(agg + (size_t)wid*128 + lane*4) = acc;
}

// ---------------- GEMM: out[r][cOff+c] = sum_k A[r][k] * W[k][cOff+c] + bias ----------------
// block: 256 threads, 64 rows, 128 cols. Optional gather (qkv comb rows) and column stats.
template<bool GATHER, bool STATS>
__global__ void gemm128_kernel(const float* __restrict__ A,
                               const float* __restrict__ hcomm, const int* __restrict__ map,
                               const float* __restrict__ W, int ldW,
                               const float* __restrict__ bias,
                               float* __restrict__ out, int ldOut,
                               int M, float* __restrict__ stats) {
    extern __shared__ float sm[];
    float* sW = sm;               // 128*128
    float* sA = sm + 128*128;     // 64*128
    float4* sW4 = (float4*)sW;
    float4* sA4 = (float4*)sA;
    const int t = threadIdx.x;
    const int cOff = blockIdx.y * 128;
    const int rowBase = blockIdx.x * 64;

    #pragma unroll
    for (int j = 0; j < 16; j++) {
        int g4 = t + j*256;
        int k = g4 >> 5, c4 = g4 & 31;
        sW4[g4] = *(const float4*)(W + (size_t)k*ldW + cOff + c4*4);
    }
    #pragma unroll
    for (int j = 0; j < 8; j++) {
        int g4 = t + j*256;
        int r = g4 >> 5, c4 = g4 & 31;
        int gr = rowBase + r;
        float4 v = make_float4(0.f, 0.f, 0.f, 0.f);
        if (gr < M) {
            if (GATHER) {
                int node = gr >> 1;
                const float* srcp;
                if (gr & 1) {
                    int cm = map[node];
                    cm = cm < 0 ? 0 : (cm > NC-1 ? NC-1 : cm);
                    srcp = hcomm + (size_t)cm*128;
                } else srcp = A + (size_t)node*128;
                v = *(const float4*)(srcp + c4*4);
            } else {
                v = *(const float4*)(A + (size_t)gr*128 + c4*4);
            }
        }
        sA4[g4] = v;
    }
    __syncthreads();

    const int lane = t & 31, warp = t >> 5;
    const int r0 = warp * 8;
    float4 acc[8];
    #pragma unroll
    for (int r = 0; r < 8; r++) acc[r] = make_float4(0.f, 0.f, 0.f, 0.f);

    #pragma unroll 2
    for (int k4 = 0; k4 < 32; k4++) {
        float4 w0 = sW4[(k4*4+0)*32 + lane];
        float4 w1 = sW4[(k4*4+1)*32 + lane];
        float4 w2 = sW4[(k4*4+2)*32 + lane];
        float4 w3 = sW4[(k4*4+3)*32 + lane];
        #pragma unroll
        for (int r = 0; r < 8; r++) {
            float4 av = sA4[(r0+r)*32 + k4];
            acc[r].x = fmaf(av.x,w0.x, fmaf(av.y,w1.x, fmaf(av.z,w2.x, fmaf(av.w,w3.x, acc[r].x))));
            acc[r].y = fmaf(av.x,w0.y, fmaf(av.y,w1.y, fmaf(av.z,w2.y, fmaf(av.w,w3.y, acc[r].y))));
            acc[r].z = fmaf(av.x,w0.z, fmaf(av.y,w1.z, fmaf(av.z,w2.z, fmaf(av.w,w3.z, acc[r].z))));
            acc[r].w = fmaf(av.x,w0.w, fmaf(av.y,w1.w, fmaf(av.z,w2.w, fmaf(av.w,w3.w, acc[r].w))));
        }
    }

    float4 bv = *(const float4*)(bias + cOff + lane*4);
    float4 psum = make_float4(0.f,0.f,0.f,0.f), psq = make_float4(0.f,0.f,0.f,0.f);
    #pragma unroll
    for (int r = 0; r < 8; r++) {
        int gr = rowBase + r0 + r;
        if (gr < M) {
            float4 o = make_float4(acc[r].x+bv.x, acc[r].y+bv.y, acc[r].z+bv.z, acc[r].w+bv.w);
            *(float4*)(out + (size_t)gr*ldOut + cOff + lane*4) = o;
            if (STATS) {
                psum.x += o.x; psum.y += o.y; psum.z += o.z; psum.w += o.w;
                psq.x += o.x*o.x; psq.y += o.y*o.y; psq.z += o.z*o.z; psq.w += o.w*o.w;
            }
        }
    }
    if (STATS) {
        __syncthreads();  // done with sA; reuse as reduction scratch
        float* sSum = sA;
        float* sSq  = sA + 128;
        if (t < 256) sA[t] = 0.f;
        __syncthreads();
        atomicAdd(&sSum[lane*4+0], psum.x); atomicAdd(&sSum[lane*4+1], psum.y);
        atomicAdd(&sSum[lane*4+2], psum.z); atomicAdd(&sSum[lane*4+3], psum.w);
        atomicAdd(&sSq [lane*4+0], psq.x);  atomicAdd(&sSq [lane*4+1], psq.y);
        atomicAdd(&sSq [lane*4+2], psq.z);  atomicAdd(&sSq [lane*4+3], psq.w);
        __syncthreads();
        if (t < 128) { atomicAdd(&stats[t], sSum[t]); atomicAdd(&stats[128+t], sSq[t]); }
    }
}

// ---------------- BN (training stats) + ReLU + optional residual ----------------
__global__ void bn_relu_res_kernel(const float* __restrict__ tin, const float* __restrict__ stats,
                                   const float* __restrict__ g, const float* __restrict__ b,
                                   const float* __restrict__ hprev, float* __restrict__ hout,
                                   int n, int residual) {
    int idx = blockIdx.x*blockDim.x + threadIdx.x;
    if (idx >= n*128) return;
    int c = idx & 127;
    float invN = 1.0f / (float)n;
    float mu = stats[c] * invN;
    float var = stats[128+c] * invN - mu*mu;
    float y = (tin[idx] - mu) / sqrtf(var + EPSV) * g[c] + b[c];
    y = fmaxf(y, 0.f);
    if (residual) y += hprev[idx];
    hout[idx] = y;
}

// ---------------- fused MHA (S=2, H=8, dh=16) + mean + residual + LayerNorm ----------------
__global__ void attn_fused_kernel(const float* __restrict__ qkv, const float* __restrict__ hnode,
                                  const float* __restrict__ WoT, const float* __restrict__ bo,
                                  const float* __restrict__ lng, const float* __restrict__ lnb,
                                  float* __restrict__ hfinal, int n) {
    extern __shared__ float sm[];
    float* sWoT = sm;              // 128*128
    float* sOm  = sm + 128*128;    // 8*128
    float4* sW4 = (float4*)sWoT;
    int t = threadIdx.x;
    #pragma unroll
    for (int j = 0; j < 16; j++) sW4[t + j*256] = ((const float4*)WoT)[t + j*256];
    __syncthreads();

    int lane = t & 31, warp = t >> 5;
    float4 bv  = ((const float4*)bo)[lane];
    float4 gv  = ((const float4*)lng)[lane];
    float4 bbv = ((const float4*)lnb)[lane];
    float* so = sOm + warp*128;

    for (int it = 0; it < 8; it++) {
        int node = blockIdx.x*64 + warp*8 + it;
        if (node >= n) break;
        const float4* row0 = (const float4*)(qkv + (size_t)(2*node)*384);
        const float4* row1 = row0 + 96;
        float4 q0 = row0[lane],    q1 = row1[lane];
        float4 k0 = row0[32+lane], k1 = row1[32+lane];
        float4 v0 = row0[64+lane], v1 = row1[64+lane];

        float s00 = q0.x*k0.x + q0.y*k0.y + q0.z*k0.z + q0.w*k0.w;
        float s01 = q0.x*k1.x + q0.y*k1.y + q0.z*k1.z + q0.w*k1.w;
        float s10 = q1.x*k0.x + q1.y*k0.y + q1.z*k0.z + q1.w*k0.w;
        float s11 = q1.x*k1.x + q1.y*k1.y + q1.z*k1.z + q1.w*k1.w;
        #pragma unroll
        for (int m = 1; m <= 2; m <<= 1) {
            s00 += __shfl_xor_sync(0xffffffffu, s00, m);
            s01 += __shfl_xor_sync(0xffffffffu, s01, m);
            s10 += __shfl_xor_sync(0xffffffffu, s10, m);
            s11 += __shfl_xor_sync(0xffffffffu, s11, m);
        }
        s00 *= 0.25f; s01 *= 0.25f; s10 *= 0.25f; s11 *= 0.25f;
        float m0 = fmaxf(s00, s01);
        float e00 = expf(s00-m0), e01 = expf(s01-m0);
        float r0i = 1.f/(e00+e01);
        float p00 = e00*r0i, p01 = e01*r0i;
        float m1 = fmaxf(s10, s11);
        float e10 = expf(s10-m1), e11 = expf(s11-m1);
        float r1i = 1.f/(e10+e11);
        float p10 = e10*r1i, p11 = e11*r1i;

        float4 om;
        om.x = 0.5f*(p00*v0.x + p01*v1.x + p10*v0.x + p11*v1.x);
        om.y = 0.5f*(p00*v0.y + p01*v1.y + p10*v0.y + p11*v1.y);
        om.z = 0.5f*(p00*v0.z + p01*v1.z + p10*v0.z + p11*v1.z);
        om.w = 0.5f*(p00*v0.w + p01*v1.w + p10*v0.w + p11*v1.w);
        ((float4*)so)[lane] = om;
        __syncwarp();

        float4 acc = ((const float4*)(hnode + (size_t)node*128))[lane];
        acc.x += bv.x; acc.y += bv.y; acc.z += bv.z; acc.w += bv.w;
        #pragma unroll 8
        for (int k = 0; k < 128; k++) {
            float ok = so[k];
            float4 wv = sW4[k*32 + lane];
            acc.x = fmaf(ok, wv.x, acc.x);
            acc.y = fmaf(ok, wv.y, acc.y);
            acc.z = fmaf(ok, wv.z, acc.z);
            acc.w = fmaf(ok, wv.w, acc.w);
        }
        float sum = acc.x+acc.y+acc.z+acc.w;
        float sq  = acc.x*acc.x + acc.y*acc.y + acc.z*acc.z + acc.w*acc.w;
        #pragma unroll
        for (int m = 16; m >= 1; m >>= 1) {
            sum += __shfl_xor_sync(0xffffffffu, sum, m);
            sq  += __shfl_xor_sync(0xffffffffu, sq, m);
        }
        float mu = sum * (1.f/128.f);
        float var = sq * (1.f/128.f) - mu*mu;
        float inv = 1.f / sqrtf(var + EPSV);
        float4 o;
        o.x = (acc.x-mu)*inv*gv.x + bbv.x;
        o.y = (acc.y-mu)*inv*gv.y + bbv.y;
        o.z = (acc.z-mu)*inv*gv.z + bbv.z;
        o.w = (acc.w-mu)*inv*gv.w + bbv.w;
        ((float4*)(hfinal + (size_t)node*128))[lane] = o;
        __syncwarp();
    }
}

// ---------------- classifier GEMM1 (128->64) + column stats ----------------
__global__ void cls_gemm1_kernel(const float* __restrict__ h, const float* __restrict__ W1,
                                 const float* __restrict__ b1, float* __restrict__ z,
                                 float* __restrict__ stats, int n) {
    __shared__ float sW[128*64];
    __shared__ float sRow[8][128];
    __shared__ float sSum[64], sSq[64];
    int t = threadIdx.x, lane = t & 31, warp = t >> 5;
    float4* sW4 = (float4*)sW;
    for (int j = t; j < 2048; j += 256) sW4[j] = ((const float4*)W1)[j];
    if (t < 64) { sSum[t] = 0.f; sSq[t] = 0.f; }
    __syncthreads();

    float2 ps = make_float2(0.f,0.f), psq = make_float2(0.f,0.f);
    float bx = b1[2*lane], by = b1[2*lane+1];
    for (int it = 0; it < 8; it++) {
        int row = blockIdx.x*64 + warp*8 + it;
        if (row < n) {
            ((float4*)sRow[warp])[lane] = ((const float4*)(h + (size_t)row*128))[lane];
            __syncwarp();
            float2 acc = make_float2(bx, by);
            #pragma unroll 8
            for (int k = 0; k < 128; k++) {
                float a = sRow[warp][k];
                float2 wv = ((float2*)sW)[k*32 + lane];
                acc.x = fmaf(a, wv.x, acc.x);
                acc.y = fmaf(a, wv.y, acc.y);
            }
            ((float2*)(z + (size_t)row*64))[lane] = acc;
            ps.x += acc.x; ps.y += acc.y;
            psq.x += acc.x*acc.x; psq.y += acc.y*acc.y;
            __syncwarp();
        }
    }
    atomicAdd(&sSum[2*lane],   ps.x); atomicAdd(&sSum[2*lane+1], ps.y);
    atomicAdd(&sSq [2*lane],   psq.x); atomicAdd(&sSq [2*lane+1], psq.y);
    __syncthreads();
    if (t < 64) { atomicAdd(&stats[t], sSum[t]); atomicAdd(&stats[64+t], sSq[t]); }
}

// ---------------- classifier: BN + ReLU + GEMM2 (64->10) + log_softmax ----------------
__global__ void cls_final_kernel(const float* __restrict__ z, const float* __restrict__ stats,
                                 const float* __restrict__ bng, const float* __restrict__ bnb,
                                 const float* __restrict__ W2, const float* __restrict__ b2,
                                 float* __restrict__ out, int n) {
    __shared__ float sW2[640];
    __shared__ float sb2[16];
    __shared__ float sZ[8][64];
    int t = threadIdx.x, lane = t & 31, warp = t >> 5;
    for (int j = t; j < 640; j += 256) sW2[j] = W2[j];
    if (t < 10) sb2[t] = b2[t];
    __syncthreads();

    float invN = 1.f / (float)n;
    int c0 = 2*lane, c1 = c0 + 1;
    float mu0 = stats[c0]*invN, mu1 = stats[c1]*invN;
    float v0 = stats[64+c0]*invN - mu0*mu0;
    float v1 = stats[64+c1]*invN - mu1*mu1;
    float sc0 = bng[c0] / sqrtf(v0 + EPSV);
    float sc1 = bng[c1] / sqrtf(v1 + EPSV);
    float sh0 = bnb[c0] - mu0*sc0;
    float sh1 = bnb[c1] - mu1*sc1;

    for (int it = 0; it < 8; it++) {
        int row = blockIdx.x*64 + warp*8 + it;
        if (row < n) {
            float2 zv = ((const float2*)(z + (size_t)row*64))[lane];
            sZ[warp][c0] = fmaxf(zv.x*sc0 + sh0, 0.f);
            sZ[warp][c1] = fmaxf(zv.y*sc1 + sh1, 0.f);
            __syncwarp();
            float logit = -1e30f;
            if (lane < 10) {
                logit = sb2[lane];
                #pragma unroll 8
                for (int k = 0; k < 64; k++) logit = fmaf(sZ[warp][k], sW2[k*10+lane], logit);
            }
            float mx = logit;
            #pragma unroll
            for (int m = 16; m >= 1; m >>= 1) mx = fmaxf(mx, __shfl_xor_sync(0xffffffffu, mx, m));
            float ex = (lane < 10) ? expf(logit - mx) : 0.f;
            float s = ex;
            #pragma unroll
            for (int m = 16; m >= 1; m >>= 1) s += __shfl_xor_sync(0xffffffffu, s, m);
            if (lane < 10) out[(size_t)row*10 + lane] = logit - mx - logf(s);
            __syncwarp();
        }
    }
}

// ---------------- host ----------------
extern "C" void kernel_launch(void* const* d_in, const int* in_sizes, int n_in,
                              void* d_out, int out_size) {
    const float* node_features = (const float*)d_in[0];
    const int*   node_ei       = (const int*)d_in[1];
    const float* comm_features = (const float*)d_in[2];
    const int*   comm_ei       = (const int*)d_in[3];
    const int*   n2c           = (const int*)d_in[4];
    const float* node_W   = (const float*)d_in[5];
    const float* node_b   = (const float*)d_in[6];
    const float* node_g   = (const float*)d_in[7];
    const float* node_be  = (const float*)d_in[8];
    const float* comm_W   = (const float*)d_in[9];
    const float* comm_b   = (const float*)d_in[10];
    const float* comm_g   = (const float*)d_in[11];
    const float* comm_be  = (const float*)d_in[12];
    const float* attn_in_w  = (const float*)d_in[13];
    const float* attn_in_b  = (const float*)d_in[14];
    const float* attn_out_w = (const float*)d_in[15];
    const float* attn_out_b = (const float*)d_in[16];
    const float* ln_g  = (const float*)d_in[17];
    const float* ln_b  = (const float*)d_in[18];
    const float* cls_W1 = (const float*)d_in[19];
    const float* cls_b1 = (const float*)d_in[20];
    const float* cls_bg = (const float*)d_in[21];
    const float* cls_bb = (const float*)d_in[22];
    const float* cls_W2 = (const float*)d_in[23];
    const float* cls_b2 = (const float*)d_in[24];
    float* out = (float*)d_out;

    float *bufA, *bufB, *agg, *tmp, *cA, *cB, *cagg, *ctmp, *qkv, *hfinal, *z1;
    float *wN, *dinvN, *wC, *dinvC, *stats, *WiT, *WoT;
    int *degN, *offN, *fillN, *colN, *degC, *offC, *fillC, *colC;
    cudaGetSymbolAddress((void**)&bufA, g_bufA);
    cudaGetSymbolAddress((void**)&bufB, g_bufB);
    cudaGetSymbolAddress((void**)&agg,  g_agg);
    cudaGetSymbolAddress((void**)&tmp,  g_tmp);
    cudaGetSymbolAddress((void**)&cA,   g_cA);
    cudaGetSymbolAddress((void**)&cB,   g_cB);
    cudaGetSymbolAddress((void**)&cagg, g_cagg);
    cudaGetSymbolAddress((void**)&ctmp, g_ctmp);
    cudaGetSymbolAddress((void**)&qkv,  g_qkv);
    cudaGetSymbolAddress((void**)&hfinal, g_hfinal);
    cudaGetSymbolAddress((void**)&z1,   g_z1);
    cudaGetSymbolAddress((void**)&degN, g_degN);
    cudaGetSymbolAddress((void**)&offN, g_offN);
    cudaGetSymbolAddress((void**)&fillN, g_fillN);
    cudaGetSymbolAddress((void**)&colN, g_colN);
    cudaGetSymbolAddress((void**)&wN,   g_wN);
    cudaGetSymbolAddress((void**)&dinvN, g_dinvN);
    cudaGetSymbolAddress((void**)&degC, g_degC);
    cudaGetSymbolAddress((void**)&offC, g_offC);
    cudaGetSymbolAddress((void**)&fillC, g_fillC);
    cudaGetSymbolAddress((void**)&colC, g_colC);
    cudaGetSymbolAddress((void**)&wC,   g_wC);
    cudaGetSymbolAddress((void**)&dinvC, g_dinvC);
    cudaGetSymbolAddress((void**)&stats, g_stats);
    cudaGetSymbolAddress((void**)&WiT,  g_WiT);
    cudaGetSymbolAddress((void**)&WoT,  g_WoT);

    cudaFuncSetAttribute(gemm128_kernel<false,true>,  cudaFuncAttributeMaxDynamicSharedMemorySize, 98304);
    cudaFuncSetAttribute(gemm128_kernel<true,false>,  cudaFuncAttributeMaxDynamicSharedMemorySize, 98304);
    cudaFuncSetAttribute(attn_fused_kernel,           cudaFuncAttributeMaxDynamicSharedMemorySize, 69632);

    // ---- graph prep ----
    zero_kernel<<<(NN+255)/256, 256>>>();
    count_deg_kernel<<<(NE+255)/256, 256>>>(node_ei + NE, degN, NE);
    count_deg_kernel<<<(CE+255)/256, 256>>>(comm_ei + CE, degC, CE);
    scan_kernel<<<1, 1024>>>(degN, offN, NN);
    scan_kernel<<<1, 1024>>>(degC, offC, NC);
    dinv_kernel<<<(NN+255)/256, 256>>>(degN, dinvN, NN);
    dinv_kernel<<<(NC+255)/256, 256>>>(degC, dinvC, NC);
    fill_csr_kernel<<<(NE+255)/256, 256>>>(node_ei, node_ei + NE, offN, fillN, colN, wN, dinvN, NE);
    fill_csr_kernel<<<(CE+255)/256, 256>>>(comm_ei, comm_ei + CE, offC, fillC, colC, wC, dinvC, CE);
    transpose_w_kernel<<<(384*128+255)/256, 256>>>(attn_in_w, attn_out_w);

    // ---- node GCN stack ----
    const float* hin = node_features;
    float* houts[3] = { bufA, bufB, bufA };
    for (int i = 0; i < 3; i++) {
        gcn_agg_kernel<<<(NN*32+255)/256, 256>>>(hin, agg, offN, colN, wN, dinvN, NN);
        gemm128_kernel<false,true><<<dim3((NN+63)/64, 1), 256, 98304>>>(
            agg, nullptr, nullptr, node_W + i*128*128, 128, node_b + i*128,
            tmp, 128, NN, stats + i*256);
        bn_relu_res_kernel<<<(NN*128+255)/256, 256>>>(
            tmp, stats + i*256, node_g + i*128, node_be + i*128, hin, houts[i], NN, i > 0);
        hin = houts[i];
    }
    const float* hnodeF = hin;  // bufA

    // ---- comm GCN stack ----
    const float* cin = comm_features;
    float* couts[3] = { cA, cB, cA };
    for (int i = 0; i < 3; i++) {
        gcn_agg_kernel<<<(NC*32+255)/256, 256>>>(cin, cagg, offC, colC, wC, dinvC, NC);
        gemm128_kernel<false,true><<<dim3((NC+63)/64, 1), 256, 98304>>>(
            cagg, nullptr, nullptr, comm_W + i*128*128, 128, comm_b + i*128,
            ctmp, 128, NC, stats + (3+i)*256);
        bn_relu_res_kernel<<<(NC*128+255)/256, 256>>>(
            ctmp, stats + (3+i)*256, comm_g + i*128, comm_be + i*128, cin, couts[i], NC, i > 0);
        cin = couts[i];
    }
    const float* hcommF = cin;  // cA

    // ---- qkv GEMM over gathered comb rows [2N x 128] @ WiT [128 x 384] ----
    gemm128_kernel<true,false><<<dim3((2*NN+63)/64, 3), 256, 98304>>>(
        hnodeF, hcommF, n2c, WiT, 384, attn_in_b, qkv, 384, 2*NN, nullptr);

    // ---- fused attention + mean + residual + LayerNorm ----
    attn_fused_kernel<<<(NN+63)/64, 256, 69632>>>(
        qkv, hnodeF, WoT, attn_out_b, ln_g, ln_b, hfinal, NN);

    // ---- classifier ----
    cls_gemm1_kernel<<<(NN+63)/64, 256>>>(hfinal, cls_W1, cls_b1, z1, stats + 6*256, NN);
    cls_final_kernel<<<(NN+63)/64, 256>>>(z1, stats + 6*256, cls_bg, cls_bb, cls_W2, cls_b2, out, NN);
}

// round 2
// speedup vs baseline: 1.2299x; 1.2299x over previous
#include <cuda_runtime.h>
#include <math.h>

#define NN 50000
#define NE 600000
#define NC 500
#define CE 8000
#define EPSV 1e-5f
#define SCAN_TILE 1024

// ---------------- scratch (static device globals; no runtime alloc) ----------------
__device__ float g_bufA[NN*128];
__device__ float g_bufB[NN*128];
__device__ float g_agg [NN*128];
__device__ float g_tmp [NN*128];
__device__ float g_cA  [NC*128];
__device__ float g_cB  [NC*128];
__device__ float g_cagg[NC*128];
__device__ float g_ctmp[NC*128];
__device__ float g_qkvN[(size_t)NN*384];
__device__ float g_qkvC[NC*384];
__device__ float g_hfinal[NN*128];
__device__ float g_z1  [NN*64];
__device__ int   g_degN [NN];
__device__ int   g_offN [NN+1];
__device__ int   g_fillN[NN];
__device__ int   g_colN [NE];
__device__ float g_wN   [NE];
__device__ float g_dinvN[NN];
__device__ int   g_degC [NC];
__device__ int   g_offC [NC+1];
__device__ int   g_fillC[NC];
__device__ int   g_colC [CE];
__device__ float g_wC   [CE];
__device__ float g_dinvC[NC];
__device__ float g_stats[7*256];
__device__ float g_WiT[128*384];
__device__ float g_WoT[128*128];
__device__ int   g_partials[128];
__device__ int   g_partoff [128];

// ---------------- graph prep ----------------
__global__ void zero_kernel() {
    int i = blockIdx.x*blockDim.x + threadIdx.x;
    if (i < NN) { g_degN[i] = 0; g_fillN[i] = 0; }
    if (i < NC) { g_degC[i] = 0; g_fillC[i] = 0; }
    if (i < 7*256) g_stats[i] = 0.f;
}

__global__ void count_deg_kernel(const int* __restrict__ dst, int* __restrict__ deg, int ne) {
    int e = blockIdx.x*blockDim.x + threadIdx.x;
    if (e < ne) atomicAdd(&deg[dst[e]], 1);
}

// ---- 3-phase parallel exclusive scan ----
// phase 1: per-block (tile=1024, 256 threads x 4) sums -> partials
__global__ void scan_partials_kernel(const int* __restrict__ cnt, int* __restrict__ partials, int n) {
    __shared__ int s[256];
    int t = threadIdx.x;
    int base = blockIdx.x * SCAN_TILE;
    int v = 0;
    #pragma unroll
    for (int j = 0; j < 4; j++) {
        int i = base + t + j*256;
        if (i < n) v += cnt[i];
    }
    s[t] = v; __syncthreads();
    for (int d = 128; d >= 1; d >>= 1) {
        if (t < d) s[t] += s[t+d];
        __syncthreads();
    }
    if (t == 0) partials[blockIdx.x] = s[0];
}

// phase 2: single warp scans <=128 partials (exclusive), writes off[n] = total
__global__ void scan_top_kernel(int* __restrict__ partials, int* __restrict__ partoff,
                                int* __restrict__ off, int n, int nb) {
    int t = threadIdx.x;  // 128 threads
    __shared__ int s[128];
    int v = (t < nb) ? partials[t] : 0;
    s[t] = v; __syncthreads();
    int acc = 0;
    for (int i = 0; i < 128; i++) { if (i == t) break; acc += s[i]; }  // small, fine
    if (t < nb) partoff[t] = acc;
    if (t == 127) off[n] = acc + v;
}

// phase 3: per-block local exclusive scan + base
__global__ void scan_final_kernel(const int* __restrict__ cnt, const int* __restrict__ partoff,
                                  int* __restrict__ off, int n) {
    __shared__ int s[256];
    int t = threadIdx.x;
    int base = blockIdx.x * SCAN_TILE;
    int v[4];
    int local = 0;
    #pragma unroll
    for (int j = 0; j < 4; j++) {
        int i = base + t*4 + j;
        v[j] = (i < n) ? cnt[i] : 0;
        local += v[j];
    }
    s[t] = local; __syncthreads();
    // exclusive scan over 256 thread-sums (Hillis-Steele)
    int x = local;
    #pragma unroll
    for (int d = 1; d < 256; d <<= 1) {
        int add = (t >= d) ? s[t-d] : 0;
        __syncthreads();
        s[t] += add;
        __syncthreads();
    }
    int tbase = partoff[blockIdx.x] + s[t] - x;
    #pragma unroll
    for (int j = 0; j < 4; j++) {
        int i = base + t*4 + j;
        if (i < n) { off[i] = tbase; tbase += v[j]; }
    }
}

__global__ void dinv_kernel(const int* __restrict__ deg, float* __restrict__ dinv, int n) {
    int i = blockIdx.x*blockDim.x + threadIdx.x;
    if (i < n) dinv[i] = 1.0f / sqrtf((float)(deg[i] + 1));  // +1 self loop
}

__global__ void fill_csr_kernel(const int* __restrict__ src, const int* __restrict__ dst,
                                const int* __restrict__ off, int* __restrict__ fill,
                                int* __restrict__ col, float* __restrict__ w,
                                const float* __restrict__ dinv, int ne) {
    int e = blockIdx.x*blockDim.x + threadIdx.x;
    if (e >= ne) return;
    int s = src[e], d = dst[e];
    int pos = off[d] + atomicAdd(&fill[d], 1);
    col[pos] = s;
    w[pos] = dinv[s] * dinv[d];
}

__global__ void transpose_w_kernel(const float* __restrict__ wi, const float* __restrict__ wo) {
    int idx = blockIdx.x*blockDim.x + threadIdx.x;
    if (idx < 384*128) { int j = idx / 128, k = idx % 128; g_WiT[k*384 + j] = wi[idx]; }
    if (idx < 128*128) { int j = idx / 128, k = idx % 128; g_WoT[k*128 + j] = wo[idx]; }
}

// ---------------- GCN aggregation: agg[i] = dinv_i^2 h[i] + sum_e w_e h[src_e] ----------------
__global__ void gcn_agg_kernel(const float* __restrict__ h, float* __restrict__ agg,
                               const int* __restrict__ off, const int* __restrict__ col,
                               const float* __restrict__ w, const float* __restrict__ dinv, int n) {
    int wid = (blockIdx.x*blockDim.x + threadIdx.x) >> 5;
    int lane = threadIdx.x & 31;
    if (wid >= n) return;
    float dv = dinv[wid];
    float sw = dv * dv;
    float4 hv = *(const float4*)(h + (size_t)wid*128 + lane*4);
    float4 acc = make_float4(sw*hv.x, sw*hv.y, sw*hv.z, sw*hv.w);
    int s = off[wid], e = off[wid+1];
    for (int j = s; j < e; j++) {
        int src = col[j];
        float ww = w[j];
        float4 xv = *(const float4*)(h + (size_t)src*128 + lane*4);
        acc.x += ww*xv.x; acc.y += ww*xv.y; acc.z += ww*xv.z; acc.w += ww*xv.w;
    }
    *(float4*)(agg + (size_t)wid*128 + lane*4) = acc;
}

// ---------------- GEMM: out[r][cOff+c] = sum_k A[r][k] * W[k][cOff+c] + bias ----------------
template<bool STATS>
__global__ void gemm128_kernel(const float* __restrict__ A,
                               const float* __restrict__ W, int ldW,
                               const float* __restrict__ bias,
                               float* __restrict__ out, int ldOut,
                               int M, float* __restrict__ stats) {
    extern __shared__ float sm[];
    float* sW = sm;               // 128*128
    float* sA = sm + 128*128;     // 64*128
    float4* sW4 = (float4*)sW;
    float4* sA4 = (float4*)sA;
    const int t = threadIdx.x;
    const int cOff = blockIdx.y * 128;
    const int rowBase = blockIdx.x * 64;

    #pragma unroll
    for (int j = 0; j < 16; j++) {
        int g4 = t + j*256;
        int k = g4 >> 5, c4 = g4 & 31;
        sW4[g4] = *(const float4*)(W + (size_t)k*ldW + cOff + c4*4);
    }
    #pragma unroll
    for (int j = 0; j < 8; j++) {
        int g4 = t + j*256;
        int r = g4 >> 5, c4 = g4 & 31;
        int gr = rowBase + r;
        float4 v = make_float4(0.f, 0.f, 0.f, 0.f);
        if (gr < M) v = *(const float4*)(A + (size_t)gr*128 + c4*4);
        sA4[g4] = v;
    }
    __syncthreads();

    const int lane = t & 31, warp = t >> 5;
    const int r0 = warp * 8;
    float4 acc[8];
    #pragma unroll
    for (int r = 0; r < 8; r++) acc[r] = make_float4(0.f, 0.f, 0.f, 0.f);

    #pragma unroll 2
    for (int k4 = 0; k4 < 32; k4++) {
        float4 w0 = sW4[(k4*4+0)*32 + lane];
        float4 w1 = sW4[(k4*4+1)*32 + lane];
        float4 w2 = sW4[(k4*4+2)*32 + lane];
        float4 w3 = sW4[(k4*4+3)*32 + lane];
        #pragma unroll
        for (int r = 0; r < 8; r++) {
            float4 av = sA4[(r0+r)*32 + k4];
            acc[r].x = fmaf(av.x,w0.x, fmaf(av.y,w1.x, fmaf(av.z,w2.x, fmaf(av.w,w3.x, acc[r].x))));
            acc[r].y = fmaf(av.x,w0.y, fmaf(av.y,w1.y, fmaf(av.z,w2.y, fmaf(av.w,w3.y, acc[r].y))));
            acc[r].z = fmaf(av.x,w0.z, fmaf(av.y,w1.z, fmaf(av.z,w2.z, fmaf(av.w,w3.z, acc[r].z))));
            acc[r].w = fmaf(av.x,w0.w, fmaf(av.y,w1.w, fmaf(av.z,w2.w, fmaf(av.w,w3.w, acc[r].w))));
        }
    }

    float4 bv = *(const float4*)(bias + cOff + lane*4);
    float4 psum = make_float4(0.f,0.f,0.f,0.f), psq = make_float4(0.f,0.f,0.f,0.f);
    #pragma unroll
    for (int r = 0; r < 8; r++) {
        int gr = rowBase + r0 + r;
        if (gr < M) {
            float4 o = make_float4(acc[r].x+bv.x, acc[r].y+bv.y, acc[r].z+bv.z, acc[r].w+bv.w);
            *(float4*)(out + (size_t)gr*ldOut + cOff + lane*4) = o;
            if (STATS) {
                psum.x += o.x; psum.y += o.y; psum.z += o.z; psum.w += o.w;
                psq.x += o.x*o.x; psq.y += o.y*o.y; psq.z += o.z*o.z; psq.w += o.w*o.w;
            }
        }
    }
    if (STATS) {
        __syncthreads();  // done with sA; reuse as reduction scratch
        float* sSum = sA;
        float* sSq  = sA + 128;
        if (t < 256) sA[t] = 0.f;
        __syncthreads();
        atomicAdd(&sSum[lane*4+0], psum.x); atomicAdd(&sSum[lane*4+1], psum.y);
        atomicAdd(&sSum[lane*4+2], psum.z); atomicAdd(&sSum[lane*4+3], psum.w);
        atomicAdd(&sSq [lane*4+0], psq.x);  atomicAdd(&sSq [lane*4+1], psq.y);
        atomicAdd(&sSq [lane*4+2], psq.z);  atomicAdd(&sSq [lane*4+3], psq.w);
        __syncthreads();
        if (t < 128) { atomicAdd(&stats[t], sSum[t]); atomicAdd(&stats[128+t], sSq[t]); }
    }
}

// ---------------- BN (training stats) + ReLU + optional residual ----------------
__global__ void bn_relu_res_kernel(const float* __restrict__ tin, const float* __restrict__ stats,
                                   const float* __restrict__ g, const float* __restrict__ b,
                                   const float* __restrict__ hprev, float* __restrict__ hout,
                                   int n, int residual) {
    int idx = blockIdx.x*blockDim.x + threadIdx.x;
    if (idx >= n*128) return;
    int c = idx & 127;
    float invN = 1.0f / (float)n;
    float mu = stats[c] * invN;
    float var = stats[128+c] * invN - mu*mu;
    float y = (tin[idx] - mu) / sqrtf(var + EPSV) * g[c] + b[c];
    y = fmaxf(y, 0.f);
    if (residual) y += hprev[idx];
    hout[idx] = y;
}

// ---------------- fused MHA (S=2, H=8, dh=16) + mean + residual + LayerNorm ----------------
__global__ void attn_fused_kernel(const float* __restrict__ qkvN, const float* __restrict__ qkvC,
                                  const int* __restrict__ map,
                                  const float* __restrict__ hnode,
                                  const float* __restrict__ WoT, const float* __restrict__ bo,
                                  const float* __restrict__ lng, const float* __restrict__ lnb,
                                  float* __restrict__ hfinal, int n) {
    extern __shared__ float sm[];
    float* sWoT = sm;              // 128*128
    float* sOm  = sm + 128*128;    // 8*128
    float4* sW4 = (float4*)sWoT;
    int t = threadIdx.x;
    #pragma unroll
    for (int j = 0; j < 16; j++) sW4[t + j*256] = ((const float4*)WoT)[t + j*256];
    __syncthreads();

    int lane = t & 31, warp = t >> 5;
    float4 bv  = ((const float4*)bo)[lane];
    float4 gv  = ((const float4*)lng)[lane];
    float4 bbv = ((const float4*)lnb)[lane];
    float* so = sOm + warp*128;

    for (int it = 0; it < 8; it++) {
        int node = blockIdx.x*64 + warp*8 + it;
        if (node >= n) break;
        int cm = map[node];
        cm = cm < 0 ? 0 : (cm > NC-1 ? NC-1 : cm);
        const float4* row0 = (const float4*)(qkvN + (size_t)node*384);
        const float4* row1 = (const float4*)(qkvC + (size_t)cm*384);
        float4 q0 = row0[lane],    q1 = row1[lane];
        float4 k0 = row0[32+lane], k1 = row1[32+lane];
        float4 v0 = row0[64+lane], v1 = row1[64+lane];

        float s00 = q0.x*k0.x + q0.y*k0.y + q0.z*k0.z + q0.w*k0.w;
        float s01 = q0.x*k1.x + q0.y*k1.y + q0.z*k1.z + q0.w*k1.w;
        float s10 = q1.x*k0.x + q1.y*k0.y + q1.z*k0.z + q1.w*k0.w;
        float s11 = q1.x*k1.x + q1.y*k1.y + q1.z*k1.z + q1.w*k1.w;
        #pragma unroll
        for (int m = 1; m <= 2; m <<= 1) {
            s00 += __shfl_xor_sync(0xffffffffu, s00, m);
            s01 += __shfl_xor_sync(0xffffffffu, s01, m);
            s10 += __shfl_xor_sync(0xffffffffu, s10, m);
            s11 += __shfl_xor_sync(0xffffffffu, s11, m);
        }
        s00 *= 0.25f; s01 *= 0.25f; s10 *= 0.25f; s11 *= 0.25f;
        float m0 = fmaxf(s00, s01);
        float e00 = expf(s00-m0), e01 = expf(s01-m0);
        float r0i = 1.f/(e00+e01);
        float p00 = e00*r0i, p01 = e01*r0i;
        float m1 = fmaxf(s10, s11);
        float e10 = expf(s10-m1), e11 = expf(s11-m1);
        float r1i = 1.f/(e10+e11);
        float p10 = e10*r1i, p11 = e11*r1i;

        float4 om;
        om.x = 0.5f*(p00*v0.x + p01*v1.x + p10*v0.x + p11*v1.x);
        om.y = 0.5f*(p00*v0.y + p01*v1.y + p10*v0.y + p11*v1.y);
        om.z = 0.5f*(p00*v0.z + p01*v1.z + p10*v0.z + p11*v1.z);
        om.w = 0.5f*(p00*v0.w + p01*v1.w + p10*v0.w + p11*v1.w);
        ((float4*)so)[lane] = om;
        __syncwarp();

        float4 acc = ((const float4*)(hnode + (size_t)node*128))[lane];
        acc.x += bv.x; acc.y += bv.y; acc.z += bv.z; acc.w += bv.w;
        #pragma unroll 8
        for (int k = 0; k < 128; k++) {
            float ok = so[k];
            float4 wv = sW4[k*32 + lane];
            acc.x = fmaf(ok, wv.x, acc.x);
            acc.y = fmaf(ok, wv.y, acc.y);
            acc.z = fmaf(ok, wv.z, acc.z);
            acc.w = fmaf(ok, wv.w, acc.w);
        }
        float sum = acc.x+acc.y+acc.z+acc.w;
        float sq  = acc.x*acc.x + acc.y*acc.y + acc.z*acc.z + acc.w*acc.w;
        #pragma unroll
        for (int m = 16; m >= 1; m >>= 1) {
            sum += __shfl_xor_sync(0xffffffffu, sum, m);
            sq  += __shfl_xor_sync(0xffffffffu, sq, m);
        }
        float mu = sum * (1.f/128.f);
        float var = sq * (1.f/128.f) - mu*mu;
        float inv = 1.f / sqrtf(var + EPSV);
        float4 o;
        o.x = (acc.x-mu)*inv*gv.x + bbv.x;
        o.y = (acc.y-mu)*inv*gv.y + bbv.y;
        o.z = (acc.z-mu)*inv*gv.z + bbv.z;
        o.w = (acc.w-mu)*inv*gv.w + bbv.w;
        ((float4*)(hfinal + (size_t)node*128))[lane] = o;
        __syncwarp();
    }
}

// ---------------- classifier GEMM1 (128->64) + column stats ----------------
__global__ void cls_gemm1_kernel(const float* __restrict__ h, const float* __restrict__ W1,
                                 const float* __restrict__ b1, float* __restrict__ z,
                                 float* __restrict__ stats, int n) {
    __shared__ float sW[128*64];
    __shared__ float sRow[8][128];
    __shared__ float sSum[64], sSq[64];
    int t = threadIdx.x, lane = t & 31, warp = t >> 5;
    float4* sW4 = (float4*)sW;
    for (int j = t; j < 2048; j += 256) sW4[j] = ((const float4*)W1)[j];
    if (t < 64) { sSum[t] = 0.f; sSq[t] = 0.f; }
    __syncthreads();

    float2 ps = make_float2(0.f,0.f), psq = make_float2(0.f,0.f);
    float bx = b1[2*lane], by = b1[2*lane+1];
    for (int it = 0; it < 8; it++) {
        int row = blockIdx.x*64 + warp*8 + it;
        if (row < n) {
            ((float4*)sRow[warp])[lane] = ((const float4*)(h + (size_t)row*128))[lane];
            __syncwarp();
            float2 acc = make_float2(bx, by);
            #pragma unroll 8
            for (int k = 0; k < 128; k++) {
                float a = sRow[warp][k];
                float2 wv = ((float2*)sW)[k*32 + lane];
                acc.x = fmaf(a, wv.x, acc.x);
                acc.y = fmaf(a, wv.y, acc.y);
            }
            ((float2*)(z + (size_t)row*64))[lane] = acc;
            ps.x += acc.x; ps.y += acc.y;
            psq.x += acc.x*acc.x; psq.y += acc.y*acc.y;
            __syncwarp();
        }
    }
    atomicAdd(&sSum[2*lane],   ps.x); atomicAdd(&sSum[2*lane+1], ps.y);
    atomicAdd(&sSq [2*lane],   psq.x); atomicAdd(&sSq [2*lane+1], psq.y);
    __syncthreads();
    if (t < 64) { atomicAdd(&stats[t], sSum[t]); atomicAdd(&stats[64+t], sSq[t]); }
}

// ---------------- classifier: BN + ReLU + GEMM2 (64->10) + log_softmax ----------------
__global__ void cls_final_kernel(const float* __restrict__ z, const float* __restrict__ stats,
                                 const float* __restrict__ bng, const float* __restrict__ bnb,
                                 const float* __restrict__ W2, const float* __restrict__ b2,
                                 float* __restrict__ out, int n) {
    __shared__ float sW2[640];
    __shared__ float sb2[16];
    __shared__ float sZ[8][64];
    int t = threadIdx.x, lane = t & 31, warp = t >> 5;
    for (int j = t; j < 640; j += 256) sW2[j] = W2[j];
    if (t < 10) sb2[t] = b2[t];
    __syncthreads();

    float invN = 1.f / (float)n;
    int c0 = 2*lane, c1 = c0 + 1;
    float mu0 = stats[c0]*invN, mu1 = stats[c1]*invN;
    float v0 = stats[64+c0]*invN - mu0*mu0;
    float v1 = stats[64+c1]*invN - mu1*mu1;
    float sc0 = bng[c0] / sqrtf(v0 + EPSV);
    float sc1 = bng[c1] / sqrtf(v1 + EPSV);
    float sh0 = bnb[c0] - mu0*sc0;
    float sh1 = bnb[c1] - mu1*sc1;

    for (int it = 0; it < 8; it++) {
        int row = blockIdx.x*64 + warp*8 + it;
        if (row < n) {
            float2 zv = ((const float2*)(z + (size_t)row*64))[lane];
            sZ[warp][c0] = fmaxf(zv.x*sc0 + sh0, 0.f);
            sZ[warp][c1] = fmaxf(zv.y*sc1 + sh1, 0.f);
            __syncwarp();
            float logit = -1e30f;
            if (lane < 10) {
                logit = sb2[lane];
                #pragma unroll 8
                for (int k = 0; k < 64; k++) logit = fmaf(sZ[warp][k], sW2[k*10+lane], logit);
            }
            float mx = logit;
            #pragma unroll
            for (int m = 16; m >= 1; m >>= 1) mx = fmaxf(mx, __shfl_xor_sync(0xffffffffu, mx, m));
            float ex = (lane < 10) ? expf(logit - mx) : 0.f;
            float s = ex;
            #pragma unroll
            for (int m = 16; m >= 1; m >>= 1) s += __shfl_xor_sync(0xffffffffu, s, m);
            if (lane < 10) out[(size_t)row*10 + lane] = logit - mx - logf(s);
            __syncwarp();
        }
    }
}

// ---------------- host ----------------
extern "C" void kernel_launch(void* const* d_in, const int* in_sizes, int n_in,
                              void* d_out, int out_size) {
    const float* node_features = (const float*)d_in[0];
    const int*   node_ei       = (const int*)d_in[1];
    const float* comm_features = (const float*)d_in[2];
    const int*   comm_ei       = (const int*)d_in[3];
    const int*   n2c           = (const int*)d_in[4];
    const float* node_W   = (const float*)d_in[5];
    const float* node_b   = (const float*)d_in[6];
    const float* node_g   = (const float*)d_in[7];
    const float* node_be  = (const float*)d_in[8];
    const float* comm_W   = (const float*)d_in[9];
    const float* comm_b   = (const float*)d_in[10];
    const float* comm_g   = (const float*)d_in[11];
    const float* comm_be  = (const float*)d_in[12];
    const float* attn_in_w  = (const float*)d_in[13];
    const float* attn_in_b  = (const float*)d_in[14];
    const float* attn_out_w = (const float*)d_in[15];
    const float* attn_out_b = (const float*)d_in[16];
    const float* ln_g  = (const float*)d_in[17];
    const float* ln_b  = (const float*)d_in[18];
    const float* cls_W1 = (const float*)d_in[19];
    const float* cls_b1 = (const float*)d_in[20];
    const float* cls_bg = (const float*)d_in[21];
    const float* cls_bb = (const float*)d_in[22];
    const float* cls_W2 = (const float*)d_in[23];
    const float* cls_b2 = (const float*)d_in[24];
    float* out = (float*)d_out;

    float *bufA, *bufB, *agg, *tmp, *cA, *cB, *cagg, *ctmp, *qkvN, *qkvC, *hfinal, *z1;
    float *wN, *dinvN, *wC, *dinvC, *stats, *WiT, *WoT;
    int *degN, *offN, *fillN, *colN, *degC, *offC, *fillC, *colC, *partials, *partoff;
    cudaGetSymbolAddress((void**)&bufA, g_bufA);
    cudaGetSymbolAddress((void**)&bufB, g_bufB);
    cudaGetSymbolAddress((void**)&agg,  g_agg);
    cudaGetSymbolAddress((void**)&tmp,  g_tmp);
    cudaGetSymbolAddress((void**)&cA,   g_cA);
    cudaGetSymbolAddress((void**)&cB,   g_cB);
    cudaGetSymbolAddress((void**)&cagg, g_cagg);
    cudaGetSymbolAddress((void**)&ctmp, g_ctmp);
    cudaGetSymbolAddress((void**)&qkvN, g_qkvN);
    cudaGetSymbolAddress((void**)&qkvC, g_qkvC);
    cudaGetSymbolAddress((void**)&hfinal, g_hfinal);
    cudaGetSymbolAddress((void**)&z1,   g_z1);
    cudaGetSymbolAddress((void**)&degN, g_degN);
    cudaGetSymbolAddress((void**)&offN, g_offN);
    cudaGetSymbolAddress((void**)&fillN, g_fillN);
    cudaGetSymbolAddress((void**)&colN, g_colN);
    cudaGetSymbolAddress((void**)&wN,   g_wN);
    cudaGetSymbolAddress((void**)&dinvN, g_dinvN);
    cudaGetSymbolAddress((void**)&degC, g_degC);
    cudaGetSymbolAddress((void**)&offC, g_offC);
    cudaGetSymbolAddress((void**)&fillC, g_fillC);
    cudaGetSymbolAddress((void**)&colC, g_colC);
    cudaGetSymbolAddress((void**)&wC,   g_wC);
    cudaGetSymbolAddress((void**)&dinvC, g_dinvC);
    cudaGetSymbolAddress((void**)&stats, g_stats);
    cudaGetSymbolAddress((void**)&WiT,  g_WiT);
    cudaGetSymbolAddress((void**)&WoT,  g_WoT);
    cudaGetSymbolAddress((void**)&partials, g_partials);
    cudaGetSymbolAddress((void**)&partoff,  g_partoff);

    cudaFuncSetAttribute(gemm128_kernel<true>,  cudaFuncAttributeMaxDynamicSharedMemorySize, 98304);
    cudaFuncSetAttribute(gemm128_kernel<false>, cudaFuncAttributeMaxDynamicSharedMemorySize, 98304);
    cudaFuncSetAttribute(attn_fused_kernel,     cudaFuncAttributeMaxDynamicSharedMemorySize, 69632);

    // ---- graph prep ----
    zero_kernel<<<(NN+255)/256, 256>>>();
    count_deg_kernel<<<(NE+255)/256, 256>>>(node_ei + NE, degN, NE);
    count_deg_kernel<<<(CE+255)/256, 256>>>(comm_ei + CE, degC, CE);
    // parallel scan for node graph
    {
        int nb = (NN + SCAN_TILE - 1) / SCAN_TILE;   // 49
        scan_partials_kernel<<<nb, 256>>>(degN, partials, NN);
        scan_top_kernel<<<1, 128>>>(partials, partoff, offN, NN, nb);
        scan_final_kernel<<<nb, 256>>>(degN, partoff, offN, NN);
    }
    {
        int nb = (NC + SCAN_TILE - 1) / SCAN_TILE;   // 1
        scan_partials_kernel<<<nb, 256>>>(degC, partials, NC);
        scan_top_kernel<<<1, 128>>>(partials, partoff, offC, NC, nb);
        scan_final_kernel<<<nb, 256>>>(degC, partoff, offC, NC);
    }
    dinv_kernel<<<(NN+255)/256, 256>>>(degN, dinvN, NN);
    dinv_kernel<<<(NC+255)/256, 256>>>(degC, dinvC, NC);
    fill_csr_kernel<<<(NE+255)/256, 256>>>(node_ei, node_ei + NE, offN, fillN, colN, wN, dinvN, NE);
    fill_csr_kernel<<<(CE+255)/256, 256>>>(comm_ei, comm_ei + CE, offC, fillC, colC, wC, dinvC, CE);
    transpose_w_kernel<<<(384*128+255)/256, 256>>>(attn_in_w, attn_out_w);

    // ---- node GCN stack ----
    const float* hin = node_features;
    float* houts[3] = { bufA, bufB, bufA };
    for (int i = 0; i < 3; i++) {
        gcn_agg_kernel<<<(NN*32+255)/256, 256>>>(hin, agg, offN, colN, wN, dinvN, NN);
        gemm128_kernel<true><<<dim3((NN+63)/64, 1), 256, 98304>>>(
            agg, node_W + i*128*128, 128, node_b + i*128,
            tmp, 128, NN, stats + i*256);
        bn_relu_res_kernel<<<(NN*128+255)/256, 256>>>(
            tmp, stats + i*256, node_g + i*128, node_be + i*128, hin, houts[i], NN, i > 0);
        hin = houts[i];
    }
    const float* hnodeF = hin;  // bufA

    // ---- comm GCN stack ----
    const float* cin = comm_features;
    float* couts[3] = { cA, cB, cA };
    for (int i = 0; i < 3; i++) {
        gcn_agg_kernel<<<(NC*32+255)/256, 256>>>(cin, cagg, offC, colC, wC, dinvC, NC);
        gemm128_kernel<true><<<dim3((NC+63)/64, 1), 256, 98304>>>(
            cagg, comm_W + i*128*128, 128, comm_b + i*128,
            ctmp, 128, NC, stats + (3+i)*256);
        bn_relu_res_kernel<<<(NC*128+255)/256, 256>>>(
            ctmp, stats + (3+i)*256, comm_g + i*128, comm_be + i*128, cin, couts[i], NC, i > 0);
        cin = couts[i];
    }
    const float* hcommF = cin;  // cA

    // ---- qkv GEMMs: node rows [N x 128] @ WiT, comm rows [500 x 128] @ WiT ----
    gemm128_kernel<false><<<dim3((NN+63)/64, 3), 256, 98304>>>(
        hnodeF, WiT, 384, attn_in_b, qkvN, 384, NN, nullptr);
    gemm128_kernel<false><<<dim3((NC+63)/64, 3), 256, 98304>>>(
        hcommF, WiT, 384, attn_in_b, qkvC, 384, NC, nullptr);

    // ---- fused attention + mean + residual + LayerNorm ----
    attn_fused_kernel<<<(NN+63)/64, 256, 69632>>>(
        qkvN, qkvC, n2c, hnodeF, WoT, attn_out_b, ln_g, ln_b, hfinal, NN);

    // ---- classifier ----
    cls_gemm1_kernel<<<(NN+63)/64, 256>>>(hfinal, cls_W1, cls_b1, z1, stats + 6*256, NN);
    cls_final_kernel<<<(NN+63)/64, 256>>>(z1, stats + 6*256, cls_bg, cls_bb, cls_W2, cls_b2, out, NN);
}